// round 6
// baseline (speedup 1.0000x reference)
#include <cuda_runtime.h>
#include <math_constants.h>

#define H 512
#define W 512
#define NB 64
#define HW (H * W)
#define NZ (2 * NB)
#define CPWARP 64           // columns per warp (32 lanes x float2)
#define NSTRIP 8            // 512 / 64
#define RPW 32              // rows per warp
#define WPB 8               // warps per block
#define NRG 2               // row groups (2 * 8 * 32 = 512 rows)

// Ping-pong skeleton buffers (134 MB each). Referenced ONLY from device code.
__device__ float g_A[(size_t)NZ * HW];
__device__ float g_B[(size_t)NZ * HW];
// Accumulators:
// [0..63] clp*t | [64..127] clp | [128..191] ts*p | [192..255] ts
// [256..319] p*t | [320..383] p | [384..447] t      (all per-batch)
__device__ float g_acc[448];

#define FINF CUDART_INF_F

struct V4 { float a, b, L, R; };  // 2 packed cols + strip-edge halo cols

// Load row r: float2 at cb; halo float2 (h0,h1): left pair on lane 0,
// right pair on lane 31 (registers shared — lanes mutually exclusive).
__device__ __forceinline__ void ldrow(const float* __restrict__ xp, int r,
                                      int cb, int c0, int lane,
                                      float2& v, float& h0, float& h1) {
    h0 = h1 = FINF;
    if ((unsigned)r < (unsigned)H) {
        v = *(const float2*)(xp + (size_t)r * W + cb);
        if (lane == 0) {
            if (c0 > 0) {
                float2 t = *(const float2*)(xp + (size_t)r * W + (c0 - 2));
                h0 = t.x; h1 = t.y;
            }
        } else if (lane == 31) {
            if (c0 + CPWARP < W) {
                float2 t = *(const float2*)(xp + (size_t)r * W + (c0 + CPWARP));
                h0 = t.x; h1 = t.y;
            }
        }
    } else {
        v.x = FINF; v.y = FINF;
    }
}

// Horizontal 3-min (+ halo cols). L valid on lane 0, R on lane 31.
__device__ __forceinline__ V4 hmin_row(float2 v, float h0, float h1, int lane) {
    float xm1 = __shfl_up_sync(0xffffffffu, v.y, 1);
    if (lane == 0) xm1 = h1;
    float xp2 = __shfl_down_sync(0xffffffffu, v.x, 1);
    if (lane == 31) xp2 = h0;
    V4 h;
    h.a = fminf(xm1, fminf(v.x, v.y));
    h.b = fminf(v.x, fminf(v.y, xp2));
    h.L = fminf(h0, fminf(h1, v.x));   // hmin at col c0-1 (lane 0)
    h.R = fminf(v.y, fminf(h0, h1));   // hmin at col c0+64 (lane 31)
    return h;
}

// Vertical 3-min -> min_pool row; -inf outside image (max-pool padding).
__device__ __forceinline__ V4 vmin3(const V4& p, const V4& q, const V4& s,
                                    bool rowok, bool ledge, bool redge) {
    V4 m;
    if (!rowok) { m.a = m.b = m.L = m.R = -FINF; return m; }
    m.a = fminf(p.a, fminf(q.a, s.a));
    m.b = fminf(p.b, fminf(q.b, s.b));
    m.L = ledge ? -FINF : fminf(p.L, fminf(q.L, s.L));
    m.R = redge ? -FINF : fminf(p.R, fminf(q.R, s.R));
    return m;
}

// Horizontal 3-max over min_pool row -> 2 valid outputs.
__device__ __forceinline__ float2 hmax_row(const V4& m, int lane) {
    float mm1 = __shfl_up_sync(0xffffffffu, m.b, 1);
    if (lane == 0) mm1 = m.L;
    float mp2 = __shfl_down_sync(0xffffffffu, m.a, 1);
    if (lane == 31) mp2 = m.R;
    float2 h;
    h.x = fmaxf(mm1, fmaxf(m.a, m.b));
    h.y = fmaxf(m.a, fmaxf(m.b, mp2));
    return h;
}

// ---------------------------------------------------------------------------
// One soft-skeletonize iteration (float2 rolling stencil, 1-row prefetch).
// mode 0: inputs -> g_A;  mode 1: g_A -> g_B;  mode 2: g_B -> g_A
// ---------------------------------------------------------------------------
__global__ void __launch_bounds__(256)
skel_step(int mode, const float* __restrict__ pred,
          const float* __restrict__ target) {
    const int z = blockIdx.y;
    const float* __restrict__ xp;
    float* __restrict__ op;
    if (mode == 0) {
        xp = (z < NB) ? pred + (size_t)z * HW : target + (size_t)(z - NB) * HW;
        op = g_A + (size_t)z * HW;
    } else if (mode == 1) {
        xp = g_A + (size_t)z * HW; op = g_B + (size_t)z * HW;
    } else {
        xp = g_B + (size_t)z * HW; op = g_A + (size_t)z * HW;
    }

    const int lane = threadIdx.x & 31;
    const int warp = threadIdx.x >> 5;
    const int c0 = blockIdx.x * CPWARP;
    const int cb = c0 + lane * 2;
    const bool ledge = (c0 == 0);
    const bool redge = (c0 + CPWARP >= W);
    const int r0 = (blockIdx.z * WPB + warp) * RPW;

    float2 v, vn; float h0, h1, h0n, h1n;
    float2 xq0, xq1;

    ldrow(xp, r0 - 2, cb, c0, lane, v, h0, h1);
    V4 hm_m2 = hmin_row(v, h0, h1, lane);
    ldrow(xp, r0 - 1, cb, c0, lane, v, h0, h1);
    V4 hm_m1 = hmin_row(v, h0, h1, lane);
    ldrow(xp, r0, cb, c0, lane, xq0, h0, h1);
    V4 hm_0 = hmin_row(xq0, h0, h1, lane);
    ldrow(xp, r0 + 1, cb, c0, lane, xq1, h0, h1);
    V4 hm_p1 = hmin_row(xq1, h0, h1, lane);

    V4 mp_m1 = vmin3(hm_m2, hm_m1, hm_0, (r0 - 1) >= 0, ledge, redge);
    V4 mp0v  = vmin3(hm_m1, hm_0, hm_p1, true, ledge, redge);
    float2 hx_m1 = hmax_row(mp_m1, lane);
    float2 hx_0  = hmax_row(mp0v, lane);
    float2 mp_0; mp_0.x = mp0v.a; mp_0.y = mp0v.b;

    // prefetch row r0+2
    ldrow(xp, r0 + 2, cb, c0, lane, vn, h0n, h1n);

    size_t off = (size_t)r0 * W + cb;
    #pragma unroll 4
    for (int r = r0; r < r0 + RPW; ++r) {
        float2 vc = vn; float hc0 = h0n, hc1 = h1n;
        ldrow(xp, r + 3, cb, c0, lane, vn, h0n, h1n);   // prefetch next row
        V4 hm_p2 = hmin_row(vc, hc0, hc1, lane);
        V4 mp_p1 = vmin3(hm_0, hm_p1, hm_p2, (r + 1) < H, ledge, redge);
        float2 hx_p1 = hmax_row(mp_p1, lane);

        float2 o;
        o.x = fmaxf(xq0.x - fmaxf(fmaxf(hx_m1.x, fmaxf(hx_0.x, hx_p1.x)) - mp_0.x, 0.0f), 0.0f);
        o.y = fmaxf(xq0.y - fmaxf(fmaxf(hx_m1.y, fmaxf(hx_0.y, hx_p1.y)) - mp_0.y, 0.0f), 0.0f);
        *(float2*)(op + off) = o;

        hx_m1 = hx_0; hx_0 = hx_p1;
        mp_0.x = mp_p1.a; mp_0.y = mp_p1.b;
        hm_0 = hm_p1; hm_p1 = hm_p2;
        xq0 = xq1; xq1 = vc;
        off += W;
    }
}

// ---------------------------------------------------------------------------
// Final iteration fused with all reductions (reads g_A; writes only g_acc).
// ---------------------------------------------------------------------------
__global__ void __launch_bounds__(256)
skel_last(const float* __restrict__ pred, const float* __restrict__ target) {
    const int z = blockIdx.y;
    const float* __restrict__ xp = g_A + (size_t)z * HW;
    const int b = (z < NB) ? z : z - NB;
    const float* __restrict__ pb = pred + (size_t)b * HW;
    const float* __restrict__ tb = target + (size_t)b * HW;

    const int lane = threadIdx.x & 31;
    const int warp = threadIdx.x >> 5;
    const int c0 = blockIdx.x * CPWARP;
    const int cb = c0 + lane * 2;
    const bool ledge = (c0 == 0);
    const bool redge = (c0 + CPWARP >= W);
    const int r0 = (blockIdx.z * WPB + warp) * RPW;

    float2 v, vn; float h0, h1, h0n, h1n;
    float2 xq0, xq1;

    ldrow(xp, r0 - 2, cb, c0, lane, v, h0, h1);
    V4 hm_m2 = hmin_row(v, h0, h1, lane);
    ldrow(xp, r0 - 1, cb, c0, lane, v, h0, h1);
    V4 hm_m1 = hmin_row(v, h0, h1, lane);
    ldrow(xp, r0, cb, c0, lane, xq0, h0, h1);
    V4 hm_0 = hmin_row(xq0, h0, h1, lane);
    ldrow(xp, r0 + 1, cb, c0, lane, xq1, h0, h1);
    V4 hm_p1 = hmin_row(xq1, h0, h1, lane);

    V4 mp_m1 = vmin3(hm_m2, hm_m1, hm_0, (r0 - 1) >= 0, ledge, redge);
    V4 mp0v  = vmin3(hm_m1, hm_0, hm_p1, true, ledge, redge);
    float2 hx_m1 = hmax_row(mp_m1, lane);
    float2 hx_0  = hmax_row(mp0v, lane);
    float2 mp_0; mp_0.x = mp0v.a; mp_0.y = mp0v.b;

    ldrow(xp, r0 + 2, cb, c0, lane, vn, h0n, h1n);

    float s0 = 0, s1 = 0, s2 = 0, s3 = 0, s4 = 0;

    size_t off = (size_t)r0 * W + cb;
    #pragma unroll 4
    for (int r = r0; r < r0 + RPW; ++r) {
        float2 vc = vn; float hc0 = h0n, hc1 = h1n;
        ldrow(xp, r + 3, cb, c0, lane, vn, h0n, h1n);
        V4 hm_p2 = hmin_row(vc, hc0, hc1, lane);
        V4 mp_p1 = vmin3(hm_0, hm_p1, hm_p2, (r + 1) < H, ledge, redge);
        float2 hx_p1 = hmax_row(mp_p1, lane);

        float2 o;
        o.x = fmaxf(xq0.x - fmaxf(fmaxf(hx_m1.x, fmaxf(hx_0.x, hx_p1.x)) - mp_0.x, 0.0f), 0.0f);
        o.y = fmaxf(xq0.y - fmaxf(fmaxf(hx_m1.y, fmaxf(hx_0.y, hx_p1.y)) - mp_0.y, 0.0f), 0.0f);

        if (z < NB) {   // o = cl_pred; accumulate dice terms too
            float2 tv = *(const float2*)(tb + off);
            float2 pv = *(const float2*)(pb + off);
            s0 += o.x * tv.x + o.y * tv.y;
            s1 += o.x + o.y;
            s2 += pv.x * tv.x + pv.y * tv.y;
            s3 += pv.x + pv.y;
            s4 += tv.x + tv.y;
        } else {        // o = target_skeleton
            float2 pv = *(const float2*)(pb + off);
            s0 += o.x * pv.x + o.y * pv.y;
            s1 += o.x + o.y;
        }

        hx_m1 = hx_0; hx_0 = hx_p1;
        mp_0.x = mp_p1.a; mp_0.y = mp_p1.b;
        hm_0 = hm_p1; hm_p1 = hm_p2;
        xq0 = xq1; xq1 = vc;
        off += W;
    }

    #pragma unroll
    for (int o = 16; o; o >>= 1) {
        s0 += __shfl_down_sync(0xffffffffu, s0, o);
        s1 += __shfl_down_sync(0xffffffffu, s1, o);
        s2 += __shfl_down_sync(0xffffffffu, s2, o);
        s3 += __shfl_down_sync(0xffffffffu, s3, o);
        s4 += __shfl_down_sync(0xffffffffu, s4, o);
    }
    __shared__ float sred[WPB][5];
    if (lane == 0) {
        sred[warp][0] = s0; sred[warp][1] = s1; sred[warp][2] = s2;
        sred[warp][3] = s3; sred[warp][4] = s4;
    }
    __syncthreads();
    if (threadIdx.x < 5) {
        float vv = 0;
        #pragma unroll
        for (int w = 0; w < WPB; w++) vv += sred[w][threadIdx.x];
        int q = threadIdx.x;
        if (z < NB) {
            int base = (q == 0) ? 0 : (q == 1) ? 64 : (q == 2) ? 256 : (q == 3) ? 320 : 384;
            atomicAdd(&g_acc[base + b], vv);
        } else if (q < 2) {
            atomicAdd(&g_acc[(q == 0 ? 128 : 192) + b], vv);
        }
    }
}

// ---------------------------------------------------------------------------
__global__ void zero_acc() {
    int i = threadIdx.x;
    if (i < 448) g_acc[i] = 0.0f;
}

__global__ void finalize_kernel(float* __restrict__ out) {
    int b = threadIdx.x;  // 64 threads
    float ifl = (g_acc[b] + 1.0f) / (g_acc[64 + b] + 1.0f);
    float tfl = (g_acc[128 + b] + 1.0f) / (g_acc[192 + b] + 1.0f);
    float it = ifl * tfl;
    float s  = ifl + tfl;
    float pt = g_acc[256 + b];
    float sp = g_acc[320 + b];
    float st = g_acc[384 + b];
    #pragma unroll
    for (int o = 16; o; o >>= 1) {
        it += __shfl_down_sync(0xffffffffu, it, o);
        s  += __shfl_down_sync(0xffffffffu, s,  o);
        pt += __shfl_down_sync(0xffffffffu, pt, o);
        sp += __shfl_down_sync(0xffffffffu, sp, o);
        st += __shfl_down_sync(0xffffffffu, st, o);
    }
    __shared__ float sh[5][2];
    if ((threadIdx.x & 31) == 0) {
        int w = threadIdx.x >> 5;
        sh[0][w] = it; sh[1][w] = s; sh[2][w] = pt; sh[3][w] = sp; sh[4][w] = st;
    }
    __syncthreads();
    if (threadIdx.x == 0) {
        float IT = sh[0][0] + sh[0][1];
        float S  = sh[1][0] + sh[1][1];
        float I  = sh[2][0] + sh[2][1];
        float Sp = sh[3][0] + sh[3][1];
        float St = sh[4][0] + sh[4][1];
        float dice   = 1.0f - (2.0f * I + 1e-6f) / (Sp + St + 1e-6f);
        float cldice = 1.0f - 2.0f * IT / S;
        out[0] = 0.8f * dice + 0.2f * cldice;
    }
}

// ---------------------------------------------------------------------------
extern "C" void kernel_launch(void* const* d_in, const int* in_sizes, int n_in,
                              void* d_out, int out_size) {
    const float* pred   = (const float*)d_in[0];
    const float* target = (const float*)d_in[1];
    float* out = (float*)d_out;

    zero_acc<<<1, 448>>>();

    dim3 blk(256);
    dim3 grd(NSTRIP, NZ, NRG);  // 8 x 128 x 2 = 2048 blocks

    // iter 1: inputs -> A
    skel_step<<<grd, blk>>>(0, pred, target);
    // iters 2..9: even -> (A->B), odd -> (B->A). After iter 9 state is in A.
    for (int k = 2; k <= 9; k++) {
        skel_step<<<grd, blk>>>((k & 1) ? 2 : 1, pred, target);
    }
    // iter 10 fused with reductions (reads A)
    skel_last<<<grd, blk>>>(pred, target);

    finalize_kernel<<<1, 64>>>(out);
}

// round 7
// speedup vs baseline: 1.8078x; 1.8078x over previous
#include <cuda_runtime.h>
#include <math_constants.h>

#define H 512
#define W 512
#define NB 64
#define HW (H * W)
#define NZ (2 * NB)
#define CPW 56              // valid output columns per warp strip
#define NSTRIP 10           // ceil(512/56)
#define RPW 32              // output rows per warp
#define WPB 8               // warps per block
#define NRG 2               // row groups: 2*8*32 = 512 rows

#define FINF CUDART_INF_F

// Ping-pong buffers (134 MB each). Referenced ONLY from device code.
__device__ float g_A[(size_t)NZ * HW];
__device__ float g_B[(size_t)NZ * HW];
// [0..63] clp*t | [64..127] clp | [128..191] ts*p | [192..255] ts
// [256..319] p*t | [320..383] p | [384..447] t   (per-batch)
__device__ float g_acc[448];

__device__ __forceinline__ float2 hmin2(float2 v) {
    float m1 = __shfl_up_sync(0xffffffffu, v.y, 1);
    float p2 = __shfl_down_sync(0xffffffffu, v.x, 1);
    return make_float2(fminf(m1, fminf(v.x, v.y)),
                       fminf(v.x, fminf(v.y, p2)));
}
__device__ __forceinline__ float2 hmax2(float2 v) {
    float m1 = __shfl_up_sync(0xffffffffu, v.y, 1);
    float p2 = __shfl_down_sync(0xffffffffu, v.x, 1);
    return make_float2(fmaxf(m1, fmaxf(v.x, v.y)),
                       fmaxf(v.x, fmaxf(v.y, p2)));
}

// Rolling soft-skeletonize pipeline state (one iteration stage).
// At base row rb: next step consumes input row rb+2, emits output row rb.
struct Pipe {
    float2 q0, q1;    // input rows rb, rb+1
    float2 hm0, hm1;  // horiz 3-min rows rb, rb+1
    float2 mp0;       // 3x3 min-pool row rb (masked -inf outside image)
    float2 hxm, hx0;  // horiz 3-max of mp rows rb-1, rb
};

// Init state at base rb from input rows rb-2..rb+1 (already +inf-masked).
__device__ __forceinline__ void pipe_init(Pipe& s, float2 va, float2 vb,
                                          float2 vc, float2 vd,
                                          int rb, bool colin) {
    float2 ha = hmin2(va), hb = hmin2(vb), hc = hmin2(vc), hd = hmin2(vd);
    bool okm = colin && (rb - 1 >= 0);     // rows >= H impossible at init
    bool ok0 = colin && (rb >= 0);
    float2 mpm, mp0;
    mpm.x = okm ? fminf(ha.x, fminf(hb.x, hc.x)) : -FINF;
    mpm.y = okm ? fminf(ha.y, fminf(hb.y, hc.y)) : -FINF;
    mp0.x = ok0 ? fminf(hb.x, fminf(hc.x, hd.x)) : -FINF;
    mp0.y = ok0 ? fminf(hb.y, fminf(hc.y, hd.y)) : -FINF;
    s.hxm = hmax2(mpm); s.hx0 = hmax2(mp0); s.mp0 = mp0;
    s.hm0 = hc; s.hm1 = hd; s.q0 = vc; s.q1 = vd;
}

// Advance one row: consume input row rb+2 (masked +inf where invalid),
// okp1 = (row rb+1 inside image) && colin. Emits output row rb.
__device__ __forceinline__ float2 pipe_step(Pipe& s, float2 vin, bool okp1) {
    float2 hmn = hmin2(vin);
    float2 mpn;
    mpn.x = okp1 ? fminf(s.hm0.x, fminf(s.hm1.x, hmn.x)) : -FINF;
    mpn.y = okp1 ? fminf(s.hm0.y, fminf(s.hm1.y, hmn.y)) : -FINF;
    float2 hxn = hmax2(mpn);
    float2 o;
    float cx = fmaxf(fmaxf(s.hxm.x, fmaxf(s.hx0.x, hxn.x)) - s.mp0.x, 0.0f);
    float cy = fmaxf(fmaxf(s.hxm.y, fmaxf(s.hx0.y, hxn.y)) - s.mp0.y, 0.0f);
    o.x = fmaxf(s.q0.x - cx, 0.0f);
    o.y = fmaxf(s.q0.y - cy, 0.0f);
    s.hxm = s.hx0; s.hx0 = hxn; s.mp0 = mpn;
    s.hm0 = s.hm1; s.hm1 = hmn;
    s.q0 = s.q1; s.q1 = vin;
    return o;
}

__device__ __forceinline__ float2 ldx(const float* __restrict__ p, int r,
                                      int gc, bool colin) {
    if (colin && (unsigned)r < (unsigned)H)
        return *(const float2*)(p + (size_t)r * W + gc);
    return make_float2(FINF, FINF);
}

// Shared set-up for both fused kernels: primes s1 (stage 1) and s2 (stage 2)
// so the main loop at row r emits out2(r).
__device__ __forceinline__ void fused_prime(const float* __restrict__ xp,
                                            Pipe& s1, Pipe& s2,
                                            int r0, int gc, bool colin) {
    pipe_init(s1, ldx(xp, r0 - 4, gc, colin), ldx(xp, r0 - 3, gc, colin),
              ldx(xp, r0 - 2, gc, colin), ldx(xp, r0 - 1, gc, colin),
              r0 - 2, colin);
    // prime stage-1 outputs y(r0-2)..y(r0+1); mp rows formed: r0-1..r0+2 (<H always)
    float2 ya = pipe_step(s1, ldx(xp, r0,     gc, colin), colin && (r0 - 1 >= 0));
    float2 yb = pipe_step(s1, ldx(xp, r0 + 1, gc, colin), colin);
    float2 yc = pipe_step(s1, ldx(xp, r0 + 2, gc, colin), colin);
    float2 yd = pipe_step(s1, ldx(xp, r0 + 3, gc, colin), colin);
    // mask y rows for stage-2 min-pool (+inf outside image / off-strip lanes)
    if (!colin || r0 - 2 < 0) ya = make_float2(FINF, FINF);
    if (!colin || r0 - 1 < 0) yb = make_float2(FINF, FINF);
    if (!colin) { yc = make_float2(FINF, FINF); yd = make_float2(FINF, FINF); }
    pipe_init(s2, ya, yb, yc, yd, r0, colin);
}

// ---------------------------------------------------------------------------
// Two fused soft-skeletonize iterations per launch.
// mode 0: inputs -> g_A;  mode 1: g_A -> g_B;  mode 2: g_B -> g_A
// ---------------------------------------------------------------------------
__global__ void __launch_bounds__(256)
skel2(int mode, const float* __restrict__ pred,
      const float* __restrict__ target) {
    const int z = blockIdx.y;
    const float* __restrict__ xp;
    float* __restrict__ op;
    if (mode == 0) {
        xp = (z < NB) ? pred + (size_t)z * HW : target + (size_t)(z - NB) * HW;
        op = g_A + (size_t)z * HW;
    } else if (mode == 1) {
        xp = g_A + (size_t)z * HW; op = g_B + (size_t)z * HW;
    } else {
        xp = g_B + (size_t)z * HW; op = g_A + (size_t)z * HW;
    }

    const int lane = threadIdx.x & 31;
    const int warp = threadIdx.x >> 5;
    const int c0 = blockIdx.x * CPW - 4;
    const int gc = c0 + lane * 2;
    const bool colin = (gc >= 0) && (gc < W);   // float2 fully in/out (gc even)
    const bool wr = (lane >= 2) && (lane <= 29) && colin;
    const int r0 = (blockIdx.z * WPB + warp) * RPW;

    Pipe s1, s2;
    fused_prime(xp, s1, s2, r0, gc, colin);

    size_t off = (size_t)r0 * W + gc;
    #pragma unroll 4
    for (int r = r0; r < r0 + RPW; ++r) {
        float2 xn = ldx(xp, r + 4, gc, colin);
        float2 y2 = pipe_step(s1, xn, colin && (r + 3 < H));   // y(r+2)
        if (!colin || (r + 2 >= H)) y2 = make_float2(FINF, FINF);
        float2 o = pipe_step(s2, y2, colin && (r + 1 < H));    // out(r)
        if (wr) *(float2*)(op + off) = o;
        off += W;
    }
}

// ---------------------------------------------------------------------------
// Final two iterations fused with all reductions (reads g_B, writes g_acc).
// ---------------------------------------------------------------------------
__global__ void __launch_bounds__(256)
skel2_last(const float* __restrict__ pred, const float* __restrict__ target) {
    const int z = blockIdx.y;
    const float* __restrict__ xp = g_B + (size_t)z * HW;
    const int b = (z < NB) ? z : z - NB;
    const float* __restrict__ pb = pred + (size_t)b * HW;
    const float* __restrict__ tb = target + (size_t)b * HW;

    const int lane = threadIdx.x & 31;
    const int warp = threadIdx.x >> 5;
    const int c0 = blockIdx.x * CPW - 4;
    const int gc = c0 + lane * 2;
    const bool colin = (gc >= 0) && (gc < W);
    const bool wr = (lane >= 2) && (lane <= 29) && colin;
    const int r0 = (blockIdx.z * WPB + warp) * RPW;

    Pipe s1, s2;
    fused_prime(xp, s1, s2, r0, gc, colin);

    float s0 = 0, s1a = 0, s2a = 0, s3 = 0, s4 = 0;

    size_t off = (size_t)r0 * W + gc;
    #pragma unroll 4
    for (int r = r0; r < r0 + RPW; ++r) {
        float2 xn = ldx(xp, r + 4, gc, colin);
        float2 y2 = pipe_step(s1, xn, colin && (r + 3 < H));
        if (!colin || (r + 2 >= H)) y2 = make_float2(FINF, FINF);
        float2 o = pipe_step(s2, y2, colin && (r + 1 < H));

        if (wr) {
            if (z < NB) {   // o = cl_pred pixels; also dice terms
                float2 tv = *(const float2*)(tb + off);
                float2 pv = *(const float2*)(pb + off);
                s0  += o.x * tv.x + o.y * tv.y;
                s1a += o.x + o.y;
                s2a += pv.x * tv.x + pv.y * tv.y;
                s3  += pv.x + pv.y;
                s4  += tv.x + tv.y;
            } else {        // o = target_skeleton pixels
                float2 pv = *(const float2*)(pb + off);
                s0  += o.x * pv.x + o.y * pv.y;
                s1a += o.x + o.y;
            }
        }
        off += W;
    }

    #pragma unroll
    for (int q = 16; q; q >>= 1) {
        s0  += __shfl_down_sync(0xffffffffu, s0, q);
        s1a += __shfl_down_sync(0xffffffffu, s1a, q);
        s2a += __shfl_down_sync(0xffffffffu, s2a, q);
        s3  += __shfl_down_sync(0xffffffffu, s3, q);
        s4  += __shfl_down_sync(0xffffffffu, s4, q);
    }
    __shared__ float sred[WPB][5];
    if (lane == 0) {
        sred[warp][0] = s0; sred[warp][1] = s1a; sred[warp][2] = s2a;
        sred[warp][3] = s3; sred[warp][4] = s4;
    }
    __syncthreads();
    if (threadIdx.x < 5) {
        float vv = 0;
        #pragma unroll
        for (int w = 0; w < WPB; w++) vv += sred[w][threadIdx.x];
        int q = threadIdx.x;
        if (z < NB) {
            int base = (q == 0) ? 0 : (q == 1) ? 64 : (q == 2) ? 256 : (q == 3) ? 320 : 384;
            atomicAdd(&g_acc[base + b], vv);
        } else if (q < 2) {
            atomicAdd(&g_acc[(q == 0 ? 128 : 192) + b], vv);
        }
    }
}

// ---------------------------------------------------------------------------
__global__ void zero_acc() {
    int i = threadIdx.x;
    if (i < 448) g_acc[i] = 0.0f;
}

__global__ void finalize_kernel(float* __restrict__ out) {
    int b = threadIdx.x;  // 64 threads
    float ifl = (g_acc[b] + 1.0f) / (g_acc[64 + b] + 1.0f);
    float tfl = (g_acc[128 + b] + 1.0f) / (g_acc[192 + b] + 1.0f);
    float it = ifl * tfl;
    float s  = ifl + tfl;
    float pt = g_acc[256 + b];
    float sp = g_acc[320 + b];
    float st = g_acc[384 + b];
    #pragma unroll
    for (int o = 16; o; o >>= 1) {
        it += __shfl_down_sync(0xffffffffu, it, o);
        s  += __shfl_down_sync(0xffffffffu, s,  o);
        pt += __shfl_down_sync(0xffffffffu, pt, o);
        sp += __shfl_down_sync(0xffffffffu, sp, o);
        st += __shfl_down_sync(0xffffffffu, st, o);
    }
    __shared__ float sh[5][2];
    if ((threadIdx.x & 31) == 0) {
        int w = threadIdx.x >> 5;
        sh[0][w] = it; sh[1][w] = s; sh[2][w] = pt; sh[3][w] = sp; sh[4][w] = st;
    }
    __syncthreads();
    if (threadIdx.x == 0) {
        float IT = sh[0][0] + sh[0][1];
        float S  = sh[1][0] + sh[1][1];
        float I  = sh[2][0] + sh[2][1];
        float Sp = sh[3][0] + sh[3][1];
        float St = sh[4][0] + sh[4][1];
        float dice   = 1.0f - (2.0f * I + 1e-6f) / (Sp + St + 1e-6f);
        float cldice = 1.0f - 2.0f * IT / S;
        out[0] = 0.8f * dice + 0.2f * cldice;
    }
}

// ---------------------------------------------------------------------------
extern "C" void kernel_launch(void* const* d_in, const int* in_sizes, int n_in,
                              void* d_out, int out_size) {
    const float* pred   = (const float*)d_in[0];
    const float* target = (const float*)d_in[1];
    float* out = (float*)d_out;

    zero_acc<<<1, 448>>>();

    dim3 blk(256);
    dim3 grd(NSTRIP, NZ, NRG);  // 10 x 128 x 2 = 2560 blocks

    // iters 1-2: inputs -> A
    skel2<<<grd, blk>>>(0, pred, target);
    // iters 3-4: A -> B
    skel2<<<grd, blk>>>(1, pred, target);
    // iters 5-6: B -> A
    skel2<<<grd, blk>>>(2, pred, target);
    // iters 7-8: A -> B
    skel2<<<grd, blk>>>(1, pred, target);
    // iters 9-10 fused with reductions (reads B)
    skel2_last<<<grd, blk>>>(pred, target);

    finalize_kernel<<<1, 64>>>(out);
}

// round 9
// speedup vs baseline: 2.2279x; 1.2324x over previous
#include <cuda_runtime.h>
#include <cuda_fp16.h>
#include <math_constants.h>
#include <cstdint>

#define H 512
#define W 512
#define NB 64
#define HW (H * W)
#define NZ (2 * NB)
#define CPW 56              // valid output columns per warp strip
#define NSTRIP 10           // ceil(512/56)
#define RPW 32              // output rows per warp
#define WPB 8               // warps per block
#define NRG 2               // row groups: 2*8*32 = 512 rows

#define FINF CUDART_INF_F

typedef unsigned int u32;

// Ping-pong fp16 buffers (67 MB each). Referenced ONLY from device code.
__device__ __half g_A[(size_t)NZ * HW];
__device__ __half g_B[(size_t)NZ * HW];
// [0..63] clp*t | [64..127] clp | [128..191] ts*p | [192..255] ts
// [256..319] p*t | [320..383] p | [384..447] t   (per-batch)
__device__ float g_acc[448];

__device__ __forceinline__ u32 h2u(__half2 v) { return *(u32*)&v; }
__device__ __forceinline__ __half2 u2h(u32 u) { return *(__half2*)&u; }

__device__ __forceinline__ __half2 inf2()  { return __float2half2_rn(FINF); }
__device__ __forceinline__ __half2 ninf2() { return __float2half2_rn(-FINF); }

// Horizontal 3-window min over cols (lane holds cols gc, gc+1).
// w.x = min(c-1,c,c+1), w.y = min(c,c+1,c+2). Edge lanes produce garbage
// (shfl wraps to own value) — discarded by the validity margin.
__device__ __forceinline__ __half2 hmin2h(__half2 v) {
    u32 u = h2u(v);
    u32 l = __shfl_up_sync(0xffffffffu, u, 1);
    u32 r = __shfl_down_sync(0xffffffffu, u, 1);
    __half2 A = u2h(__byte_perm(l, u, 0x5432));   // (left.y, v.x)
    __half2 B = u2h(__byte_perm(u, r, 0x5432));   // (v.y, right.x)
    return __hmin2(A, __hmin2(v, B));
}
__device__ __forceinline__ __half2 hmax2h(__half2 v) {
    u32 u = h2u(v);
    u32 l = __shfl_up_sync(0xffffffffu, u, 1);
    u32 r = __shfl_down_sync(0xffffffffu, u, 1);
    __half2 A = u2h(__byte_perm(l, u, 0x5432));
    __half2 B = u2h(__byte_perm(u, r, 0x5432));
    return __hmax2(A, __hmax2(v, B));
}

// Rolling soft-skeletonize pipeline (one iteration stage).
// At base row rb: next step consumes input row rb+2, emits output row rb.
struct Pipe {
    __half2 q0, q1;    // input rows rb, rb+1
    __half2 hm0, hm1;  // horiz 3-min rows rb, rb+1
    __half2 mp0;       // 3x3 min-pool row rb (-inf outside image)
    __half2 hxm, hx0;  // horiz 3-max of mp rows rb-1, rb
};

__device__ __forceinline__ void pipe_init(Pipe& s, __half2 va, __half2 vb,
                                          __half2 vc, __half2 vd,
                                          int rb, bool colin) {
    __half2 ha = hmin2h(va), hb = hmin2h(vb), hc = hmin2h(vc), hd = hmin2h(vd);
    bool okm = colin && (rb - 1 >= 0);
    bool ok0 = colin && (rb >= 0);
    __half2 mpm = okm ? __hmin2(ha, __hmin2(hb, hc)) : ninf2();
    __half2 mp0 = ok0 ? __hmin2(hb, __hmin2(hc, hd)) : ninf2();
    s.hxm = hmax2h(mpm); s.hx0 = hmax2h(mp0); s.mp0 = mp0;
    s.hm0 = hc; s.hm1 = hd; s.q0 = vc; s.q1 = vd;
}

// Advance one row: consume input row rb+2 (+inf-masked if invalid),
// okp1 = (row rb+1 in image) && colin. Emits output row rb.
__device__ __forceinline__ __half2 pipe_step(Pipe& s, __half2 vin, bool okp1) {
    __half2 hmn = hmin2h(vin);
    __half2 mpn = okp1 ? __hmin2(s.hm0, __hmin2(s.hm1, hmn)) : ninf2();
    __half2 hxn = hmax2h(mpn);
    __half2 z = __float2half2_rn(0.0f);
    __half2 mx = __hmax2(s.hxm, __hmax2(s.hx0, hxn));
    __half2 contour = __hmax2(__hsub2(mx, s.mp0), z);
    __half2 o = __hmax2(__hsub2(s.q0, contour), z);
    s.hxm = s.hx0; s.hx0 = hxn; s.mp0 = mpn;
    s.hm0 = s.hm1; s.hm1 = hmn;
    s.q0 = s.q1; s.q1 = vin;
    return o;
}

// fp16 source load (middle/last kernels)
__device__ __forceinline__ __half2 ldh(const __half* __restrict__ p, int r,
                                       int gc, bool colin) {
    if (colin && (unsigned)r < (unsigned)H)
        return *(const __half2*)(p + (size_t)r * W + gc);
    return inf2();
}
// fp32 source load + convert (first kernel)
__device__ __forceinline__ __half2 ldf(const float* __restrict__ p, int r,
                                       int gc, bool colin) {
    if (colin && (unsigned)r < (unsigned)H) {
        float2 f = *(const float2*)(p + (size_t)r * W + gc);
        return __floats2half2_rn(f.x, f.y);
    }
    return inf2();
}

// Prime both stages so the main loop at row r emits out2(r).
template <typename LD>
__device__ __forceinline__ void fused_prime(LD ld, Pipe& s1, Pipe& s2,
                                            int r0, bool colin) {
    pipe_init(s1, ld(r0 - 4), ld(r0 - 3), ld(r0 - 2), ld(r0 - 1), r0 - 2, colin);
    __half2 ya = pipe_step(s1, ld(r0),     colin && (r0 - 1 >= 0));
    __half2 yb = pipe_step(s1, ld(r0 + 1), colin);
    __half2 yc = pipe_step(s1, ld(r0 + 2), colin);
    __half2 yd = pipe_step(s1, ld(r0 + 3), colin);
    if (!colin || r0 - 2 < 0) ya = inf2();
    if (!colin || r0 - 1 < 0) yb = inf2();
    if (!colin) { yc = inf2(); yd = inf2(); }
    pipe_init(s2, ya, yb, yc, yd, r0, colin);
}

// ---------------------------------------------------------------------------
// Two fused soft-skeletonize iterations per launch.
// mode 0: fp32 inputs -> g_A;  mode 1: g_A -> g_B;  mode 2: g_B -> g_A
// ---------------------------------------------------------------------------
__global__ void __launch_bounds__(256)
skel2(int mode, const float* __restrict__ pred,
      const float* __restrict__ target) {
    const int z = blockIdx.y;
    const int lane = threadIdx.x & 31;
    const int warp = threadIdx.x >> 5;
    const int c0 = blockIdx.x * CPW - 4;
    const int gc = c0 + lane * 2;
    const bool colin = (gc >= 0) && (gc < W);
    const bool wr = (lane >= 2) && (lane <= 29) && colin;
    const int r0 = (blockIdx.z * WPB + warp) * RPW;

    const float* __restrict__ xf = nullptr;
    const __half* __restrict__ xh = nullptr;
    __half* __restrict__ op;
    if (mode == 0) {
        xf = (z < NB) ? pred + (size_t)z * HW : target + (size_t)(z - NB) * HW;
        op = g_A + (size_t)z * HW;
    } else if (mode == 1) {
        xh = g_A + (size_t)z * HW; op = g_B + (size_t)z * HW;
    } else {
        xh = g_B + (size_t)z * HW; op = g_A + (size_t)z * HW;
    }

    Pipe s1, s2;
    size_t off = (size_t)r0 * W + gc;

    if (mode == 0) {
        auto ld = [&](int r) { return ldf(xf, r, gc, colin); };
        fused_prime(ld, s1, s2, r0, colin);
        #pragma unroll 4
        for (int r = r0; r < r0 + RPW; ++r) {
            __half2 y2 = pipe_step(s1, ld(r + 4), colin && (r + 3 < H));
            if (!colin || (r + 2 >= H)) y2 = inf2();
            __half2 o = pipe_step(s2, y2, colin && (r + 1 < H));
            if (wr) *(__half2*)(op + off) = o;
            off += W;
        }
    } else {
        auto ld = [&](int r) { return ldh(xh, r, gc, colin); };
        fused_prime(ld, s1, s2, r0, colin);
        #pragma unroll 4
        for (int r = r0; r < r0 + RPW; ++r) {
            __half2 y2 = pipe_step(s1, ld(r + 4), colin && (r + 3 < H));
            if (!colin || (r + 2 >= H)) y2 = inf2();
            __half2 o = pipe_step(s2, y2, colin && (r + 1 < H));
            if (wr) *(__half2*)(op + off) = o;
            off += W;
        }
    }
}

// ---------------------------------------------------------------------------
// Final two iterations fused with all reductions (reads g_B, writes g_acc).
// ---------------------------------------------------------------------------
__global__ void __launch_bounds__(256)
skel2_last(const float* __restrict__ pred, const float* __restrict__ target) {
    const int z = blockIdx.y;
    const __half* __restrict__ xp = g_B + (size_t)z * HW;
    const int b = (z < NB) ? z : z - NB;
    const float* __restrict__ pb = pred + (size_t)b * HW;
    const float* __restrict__ tb = target + (size_t)b * HW;

    const int lane = threadIdx.x & 31;
    const int warp = threadIdx.x >> 5;
    const int c0 = blockIdx.x * CPW - 4;
    const int gc = c0 + lane * 2;
    const bool colin = (gc >= 0) && (gc < W);
    const bool wr = (lane >= 2) && (lane <= 29) && colin;
    const int r0 = (blockIdx.z * WPB + warp) * RPW;

    Pipe s1, s2;
    auto ld = [&](int r) { return ldh(xp, r, gc, colin); };
    fused_prime(ld, s1, s2, r0, colin);

    float s0 = 0, s1a = 0, s2a = 0, s3 = 0, s4 = 0;

    size_t off = (size_t)r0 * W + gc;
    #pragma unroll 4
    for (int r = r0; r < r0 + RPW; ++r) {
        __half2 y2 = pipe_step(s1, ld(r + 4), colin && (r + 3 < H));
        if (!colin || (r + 2 >= H)) y2 = inf2();
        __half2 o2 = pipe_step(s2, y2, colin && (r + 1 < H));

        if (wr) {
            float2 o = __half22float2(o2);
            if (z < NB) {   // o = cl_pred pixels; also dice terms (exact fp32)
                float2 tv = *(const float2*)(tb + off);
                float2 pv = *(const float2*)(pb + off);
                s0  += o.x * tv.x + o.y * tv.y;
                s1a += o.x + o.y;
                s2a += pv.x * tv.x + pv.y * tv.y;
                s3  += pv.x + pv.y;
                s4  += tv.x + tv.y;
            } else {        // o = target_skeleton pixels
                float2 pv = *(const float2*)(pb + off);
                s0  += o.x * pv.x + o.y * pv.y;
                s1a += o.x + o.y;
            }
        }
        off += W;
    }

    #pragma unroll
    for (int q = 16; q; q >>= 1) {
        s0  += __shfl_down_sync(0xffffffffu, s0, q);
        s1a += __shfl_down_sync(0xffffffffu, s1a, q);
        s2a += __shfl_down_sync(0xffffffffu, s2a, q);
        s3  += __shfl_down_sync(0xffffffffu, s3, q);
        s4  += __shfl_down_sync(0xffffffffu, s4, q);
    }
    __shared__ float sred[WPB][5];
    if (lane == 0) {
        sred[warp][0] = s0; sred[warp][1] = s1a; sred[warp][2] = s2a;
        sred[warp][3] = s3; sred[warp][4] = s4;
    }
    __syncthreads();
    if (threadIdx.x < 5) {
        float vv = 0;
        #pragma unroll
        for (int w = 0; w < WPB; w++) vv += sred[w][threadIdx.x];
        int q = threadIdx.x;
        if (z < NB) {
            int base = (q == 0) ? 0 : (q == 1) ? 64 : (q == 2) ? 256 : (q == 3) ? 320 : 384;
            atomicAdd(&g_acc[base + b], vv);
        } else if (q < 2) {
            atomicAdd(&g_acc[(q == 0 ? 128 : 192) + b], vv);
        }
    }
}

// ---------------------------------------------------------------------------
__global__ void zero_acc() {
    int i = threadIdx.x;
    if (i < 448) g_acc[i] = 0.0f;
}

__global__ void finalize_kernel(float* __restrict__ out) {
    int b = threadIdx.x;  // 64 threads
    float ifl = (g_acc[b] + 1.0f) / (g_acc[64 + b] + 1.0f);
    float tfl = (g_acc[128 + b] + 1.0f) / (g_acc[192 + b] + 1.0f);
    float it = ifl * tfl;
    float s  = ifl + tfl;
    float pt = g_acc[256 + b];
    float sp = g_acc[320 + b];
    float st = g_acc[384 + b];
    #pragma unroll
    for (int o = 16; o; o >>= 1) {
        it += __shfl_down_sync(0xffffffffu, it, o);
        s  += __shfl_down_sync(0xffffffffu, s,  o);
        pt += __shfl_down_sync(0xffffffffu, pt, o);
        sp += __shfl_down_sync(0xffffffffu, sp, o);
        st += __shfl_down_sync(0xffffffffu, st, o);
    }
    __shared__ float sh[5][2];
    if ((threadIdx.x & 31) == 0) {
        int w = threadIdx.x >> 5;
        sh[0][w] = it; sh[1][w] = s; sh[2][w] = pt; sh[3][w] = sp; sh[4][w] = st;
    }
    __syncthreads();
    if (threadIdx.x == 0) {
        float IT = sh[0][0] + sh[0][1];
        float S  = sh[1][0] + sh[1][1];
        float I  = sh[2][0] + sh[2][1];
        float Sp = sh[3][0] + sh[3][1];
        float St = sh[4][0] + sh[4][1];
        float dice   = 1.0f - (2.0f * I + 1e-6f) / (Sp + St + 1e-6f);
        float cldice = 1.0f - 2.0f * IT / S;
        out[0] = 0.8f * dice + 0.2f * cldice;
    }
}

// ---------------------------------------------------------------------------
extern "C" void kernel_launch(void* const* d_in, const int* in_sizes, int n_in,
                              void* d_out, int out_size) {
    const float* pred   = (const float*)d_in[0];
    const float* target = (const float*)d_in[1];
    float* out = (float*)d_out;

    zero_acc<<<1, 448>>>();

    dim3 blk(256);
    dim3 grd(NSTRIP, NZ, NRG);  // 10 x 128 x 2 = 2560 blocks

    skel2<<<grd, blk>>>(0, pred, target);   // iters 1-2: inputs -> A
    skel2<<<grd, blk>>>(1, pred, target);   // iters 3-4: A -> B
    skel2<<<grd, blk>>>(2, pred, target);   // iters 5-6: B -> A
    skel2<<<grd, blk>>>(1, pred, target);   // iters 7-8: A -> B
    skel2_last<<<grd, blk>>>(pred, target); // iters 9-10 + reductions (reads B)

    finalize_kernel<<<1, 64>>>(out);
}

// round 10
// speedup vs baseline: 2.3809x; 1.0687x over previous
#include <cuda_runtime.h>
#include <cuda_fp16.h>
#include <math_constants.h>
#include <cstdint>

#define H 512
#define W 512
#define NB 64
#define HW (H * W)
#define NZ (2 * NB)
#define CPW 120             // valid output columns per warp strip
#define NSTRIP 5            // ceil(512/120)
#define RPW 32              // output rows per warp
#define WPB 8               // warps per block
#define NRG 2               // row groups: 2*8*32 = 512 rows

#define FINF CUDART_INF_F

typedef unsigned int u32;

// Ping-pong fp16 buffers (67 MB each). Referenced ONLY from device code.
__device__ __half g_A[(size_t)NZ * HW];
__device__ __half g_B[(size_t)NZ * HW];
// [0..63] clp*t | [64..127] clp | [128..191] ts*p | [192..255] ts
// [256..319] p*t | [320..383] p | [384..447] t   (per-batch)
__device__ float g_acc[448];

__device__ __forceinline__ u32 h2u(__half2 v) { return *(u32*)&v; }
__device__ __forceinline__ __half2 u2h(u32 u) { return *(__half2*)&u; }

// 4 packed columns per lane: lo = (c0,c1), hi = (c2,c3)
struct W4 { __half2 lo, hi; };

__device__ __forceinline__ W4 bcast4(float f) {
    W4 w; w.lo = __float2half2_rn(f); w.hi = w.lo; return w;
}
__device__ __forceinline__ W4 inf4()  { return bcast4(FINF); }
__device__ __forceinline__ W4 ninf4() { return bcast4(-FINF); }

__device__ __forceinline__ W4 min3w(const W4& a, const W4& b, const W4& c) {
    W4 r;
    r.lo = __hmin2(a.lo, __hmin2(b.lo, c.lo));
    r.hi = __hmin2(a.hi, __hmin2(b.hi, c.hi));
    return r;
}
__device__ __forceinline__ W4 max3w(const W4& a, const W4& b, const W4& c) {
    W4 r;
    r.lo = __hmax2(a.lo, __hmax2(b.lo, c.lo));
    r.hi = __hmax2(a.hi, __hmax2(b.hi, c.hi));
    return r;
}

// Horizontal 3-window min over 4 packed cols.
// w[c] = min(x[c-1], x[c], x[c+1]); warp-edge lanes contaminated (wrap) —
// discarded via the 4-col validity margin per fused pair.
__device__ __forceinline__ W4 hmin4(const W4& v) {
    u32 ulo = h2u(v.lo), uhi = h2u(v.hi);
    u32 lhi = __shfl_up_sync(0xffffffffu, uhi, 1);    // left lane's (c2,c3)
    u32 rlo = __shfl_down_sync(0xffffffffu, ulo, 1);  // right lane's (c0,c1)
    __half2 mid = u2h(__byte_perm(ulo, uhi, 0x5432)); // (x1, x2)
    __half2 shl = u2h(__byte_perm(lhi, ulo, 0x5432)); // (x-1, x0)
    __half2 shr = u2h(__byte_perm(uhi, rlo, 0x5432)); // (x3, x4)
    W4 h;
    h.lo = __hmin2(shl, __hmin2(v.lo, mid));
    h.hi = __hmin2(mid, __hmin2(v.hi, shr));
    return h;
}
__device__ __forceinline__ W4 hmax4(const W4& v) {
    u32 ulo = h2u(v.lo), uhi = h2u(v.hi);
    u32 lhi = __shfl_up_sync(0xffffffffu, uhi, 1);
    u32 rlo = __shfl_down_sync(0xffffffffu, ulo, 1);
    __half2 mid = u2h(__byte_perm(ulo, uhi, 0x5432));
    __half2 shl = u2h(__byte_perm(lhi, ulo, 0x5432));
    __half2 shr = u2h(__byte_perm(uhi, rlo, 0x5432));
    W4 h;
    h.lo = __hmax2(shl, __hmax2(v.lo, mid));
    h.hi = __hmax2(mid, __hmax2(v.hi, shr));
    return h;
}

// Rolling soft-skeletonize pipeline (one iteration stage).
// At base row rb: next step consumes input row rb+2, emits output row rb.
struct Pipe {
    W4 q0, q1;    // input rows rb, rb+1
    W4 hm0, hm1;  // horiz 3-min rows rb, rb+1
    W4 mp0;       // 3x3 min-pool row rb (-inf outside image)
    W4 hxm, hx0;  // horiz 3-max of mp rows rb-1, rb
};

__device__ __forceinline__ void pipe_init(Pipe& s, const W4& va, const W4& vb,
                                          const W4& vc, const W4& vd,
                                          int rb, bool colin) {
    W4 ha = hmin4(va), hb = hmin4(vb), hc = hmin4(vc), hd = hmin4(vd);
    bool okm = colin && (rb - 1 >= 0);
    bool ok0 = colin && (rb >= 0);
    W4 mpm = okm ? min3w(ha, hb, hc) : ninf4();
    W4 mp0 = ok0 ? min3w(hb, hc, hd) : ninf4();
    s.hxm = hmax4(mpm); s.hx0 = hmax4(mp0); s.mp0 = mp0;
    s.hm0 = hc; s.hm1 = hd; s.q0 = vc; s.q1 = vd;
}

// Advance one row: consume input row rb+2 (+inf-masked if invalid),
// okp1 = (row rb+1 in image) && colin. Emits output row rb.
__device__ __forceinline__ W4 pipe_step(Pipe& s, const W4& vin, bool okp1) {
    W4 hmn = hmin4(vin);
    W4 mpn = okp1 ? min3w(s.hm0, s.hm1, hmn) : ninf4();
    W4 hxn = hmax4(mpn);
    W4 mx = max3w(s.hxm, s.hx0, hxn);
    __half2 z = __float2half2_rn(0.0f);
    W4 o;
    o.lo = __hmax2(__hsub2(s.q0.lo, __hmax2(__hsub2(mx.lo, s.mp0.lo), z)), z);
    o.hi = __hmax2(__hsub2(s.q0.hi, __hmax2(__hsub2(mx.hi, s.mp0.hi), z)), z);
    s.hxm = s.hx0; s.hx0 = hxn; s.mp0 = mpn;
    s.hm0 = s.hm1; s.hm1 = hmn;
    s.q0 = s.q1; s.q1 = vin;
    return o;
}

// fp16 source load (middle/last kernels): 8B per lane
__device__ __forceinline__ W4 ldh4(const __half* __restrict__ p, int r,
                                   int gc, bool colin) {
    if (colin && (unsigned)r < (unsigned)H) {
        uint2 t = *(const uint2*)(p + (size_t)r * W + gc);
        W4 w; w.lo = u2h(t.x); w.hi = u2h(t.y); return w;
    }
    return inf4();
}
// fp32 source load + convert (first kernel): 16B per lane
__device__ __forceinline__ W4 ldf4(const float* __restrict__ p, int r,
                                   int gc, bool colin) {
    if (colin && (unsigned)r < (unsigned)H) {
        float4 f = *(const float4*)(p + (size_t)r * W + gc);
        W4 w; w.lo = __floats2half2_rn(f.x, f.y);
        w.hi = __floats2half2_rn(f.z, f.w); return w;
    }
    return inf4();
}

// Prime both stages so the main loop at row r emits out2(r).
template <typename LD>
__device__ __forceinline__ void fused_prime(LD ld, Pipe& s1, Pipe& s2,
                                            int r0, bool colin) {
    pipe_init(s1, ld(r0 - 4), ld(r0 - 3), ld(r0 - 2), ld(r0 - 1), r0 - 2, colin);
    W4 ya = pipe_step(s1, ld(r0),     colin && (r0 - 1 >= 0));
    W4 yb = pipe_step(s1, ld(r0 + 1), colin);
    W4 yc = pipe_step(s1, ld(r0 + 2), colin);
    W4 yd = pipe_step(s1, ld(r0 + 3), colin);
    if (!colin || r0 - 2 < 0) ya = inf4();
    if (!colin || r0 - 1 < 0) yb = inf4();
    if (!colin) { yc = inf4(); yd = inf4(); }
    pipe_init(s2, ya, yb, yc, yd, r0, colin);
}

// ---------------------------------------------------------------------------
// Two fused soft-skeletonize iterations per launch.
// mode 0: fp32 inputs -> g_A;  mode 1: g_A -> g_B;  mode 2: g_B -> g_A
// ---------------------------------------------------------------------------
__global__ void __launch_bounds__(256)
skel2(int mode, const float* __restrict__ pred,
      const float* __restrict__ target) {
    const int z = blockIdx.y;
    const int lane = threadIdx.x & 31;
    const int warp = threadIdx.x >> 5;
    const int c0 = blockIdx.x * CPW - 4;
    const int gc = c0 + lane * 4;
    const bool colin = (gc >= 0) && (gc < W);   // 4-col group fully in/out
    const bool wr = (lane >= 1) && (lane <= 30) && colin;
    const int r0 = (blockIdx.z * WPB + warp) * RPW;

    const float* __restrict__ xf = nullptr;
    const __half* __restrict__ xh = nullptr;
    __half* __restrict__ op;
    if (mode == 0) {
        xf = (z < NB) ? pred + (size_t)z * HW : target + (size_t)(z - NB) * HW;
        op = g_A + (size_t)z * HW;
    } else if (mode == 1) {
        xh = g_A + (size_t)z * HW; op = g_B + (size_t)z * HW;
    } else {
        xh = g_B + (size_t)z * HW; op = g_A + (size_t)z * HW;
    }

    Pipe s1, s2;
    size_t off = (size_t)r0 * W + gc;

    if (mode == 0) {
        auto ld = [&](int r) { return ldf4(xf, r, gc, colin); };
        fused_prime(ld, s1, s2, r0, colin);
        #pragma unroll 4
        for (int r = r0; r < r0 + RPW; ++r) {
            W4 y2 = pipe_step(s1, ld(r + 4), colin && (r + 3 < H));
            if (!colin || (r + 2 >= H)) y2 = inf4();
            W4 o = pipe_step(s2, y2, colin && (r + 1 < H));
            if (wr) {
                uint2 st; st.x = h2u(o.lo); st.y = h2u(o.hi);
                *(uint2*)(op + off) = st;
            }
            off += W;
        }
    } else {
        auto ld = [&](int r) { return ldh4(xh, r, gc, colin); };
        fused_prime(ld, s1, s2, r0, colin);
        #pragma unroll 4
        for (int r = r0; r < r0 + RPW; ++r) {
            W4 y2 = pipe_step(s1, ld(r + 4), colin && (r + 3 < H));
            if (!colin || (r + 2 >= H)) y2 = inf4();
            W4 o = pipe_step(s2, y2, colin && (r + 1 < H));
            if (wr) {
                uint2 st; st.x = h2u(o.lo); st.y = h2u(o.hi);
                *(uint2*)(op + off) = st;
            }
            off += W;
        }
    }
}

// ---------------------------------------------------------------------------
// Final two iterations fused with all reductions (reads g_B, writes g_acc).
// ---------------------------------------------------------------------------
__global__ void __launch_bounds__(256)
skel2_last(const float* __restrict__ pred, const float* __restrict__ target) {
    const int z = blockIdx.y;
    const __half* __restrict__ xp = g_B + (size_t)z * HW;
    const int b = (z < NB) ? z : z - NB;
    const float* __restrict__ pb = pred + (size_t)b * HW;
    const float* __restrict__ tb = target + (size_t)b * HW;

    const int lane = threadIdx.x & 31;
    const int warp = threadIdx.x >> 5;
    const int c0 = blockIdx.x * CPW - 4;
    const int gc = c0 + lane * 4;
    const bool colin = (gc >= 0) && (gc < W);
    const bool wr = (lane >= 1) && (lane <= 30) && colin;
    const int r0 = (blockIdx.z * WPB + warp) * RPW;

    Pipe s1, s2;
    auto ld = [&](int r) { return ldh4(xp, r, gc, colin); };
    fused_prime(ld, s1, s2, r0, colin);

    float s0 = 0, s1a = 0, s2a = 0, s3 = 0, s4 = 0;

    size_t off = (size_t)r0 * W + gc;
    #pragma unroll 4
    for (int r = r0; r < r0 + RPW; ++r) {
        W4 y2 = pipe_step(s1, ld(r + 4), colin && (r + 3 < H));
        if (!colin || (r + 2 >= H)) y2 = inf4();
        W4 o4 = pipe_step(s2, y2, colin && (r + 1 < H));

        if (wr) {
            float2 oa = __half22float2(o4.lo);
            float2 ob = __half22float2(o4.hi);
            if (z < NB) {   // o = cl_pred pixels; also dice terms (exact fp32)
                float4 tv = *(const float4*)(tb + off);
                float4 pv = *(const float4*)(pb + off);
                s0  += oa.x * tv.x + oa.y * tv.y + ob.x * tv.z + ob.y * tv.w;
                s1a += oa.x + oa.y + ob.x + ob.y;
                s2a += pv.x * tv.x + pv.y * tv.y + pv.z * tv.z + pv.w * tv.w;
                s3  += pv.x + pv.y + pv.z + pv.w;
                s4  += tv.x + tv.y + tv.z + tv.w;
            } else {        // o = target_skeleton pixels
                float4 pv = *(const float4*)(pb + off);
                s0  += oa.x * pv.x + oa.y * pv.y + ob.x * pv.z + ob.y * pv.w;
                s1a += oa.x + oa.y + ob.x + ob.y;
            }
        }
        off += W;
    }

    #pragma unroll
    for (int q = 16; q; q >>= 1) {
        s0  += __shfl_down_sync(0xffffffffu, s0, q);
        s1a += __shfl_down_sync(0xffffffffu, s1a, q);
        s2a += __shfl_down_sync(0xffffffffu, s2a, q);
        s3  += __shfl_down_sync(0xffffffffu, s3, q);
        s4  += __shfl_down_sync(0xffffffffu, s4, q);
    }
    __shared__ float sred[WPB][5];
    if (lane == 0) {
        sred[warp][0] = s0; sred[warp][1] = s1a; sred[warp][2] = s2a;
        sred[warp][3] = s3; sred[warp][4] = s4;
    }
    __syncthreads();
    if (threadIdx.x < 5) {
        float vv = 0;
        #pragma unroll
        for (int w = 0; w < WPB; w++) vv += sred[w][threadIdx.x];
        int q = threadIdx.x;
        if (z < NB) {
            int base = (q == 0) ? 0 : (q == 1) ? 64 : (q == 2) ? 256 : (q == 3) ? 320 : 384;
            atomicAdd(&g_acc[base + b], vv);
        } else if (q < 2) {
            atomicAdd(&g_acc[(q == 0 ? 128 : 192) + b], vv);
        }
    }
}

// ---------------------------------------------------------------------------
__global__ void zero_acc() {
    int i = threadIdx.x;
    if (i < 448) g_acc[i] = 0.0f;
}

__global__ void finalize_kernel(float* __restrict__ out) {
    int b = threadIdx.x;  // 64 threads
    float ifl = (g_acc[b] + 1.0f) / (g_acc[64 + b] + 1.0f);
    float tfl = (g_acc[128 + b] + 1.0f) / (g_acc[192 + b] + 1.0f);
    float it = ifl * tfl;
    float s  = ifl + tfl;
    float pt = g_acc[256 + b];
    float sp = g_acc[320 + b];
    float st = g_acc[384 + b];
    #pragma unroll
    for (int o = 16; o; o >>= 1) {
        it += __shfl_down_sync(0xffffffffu, it, o);
        s  += __shfl_down_sync(0xffffffffu, s,  o);
        pt += __shfl_down_sync(0xffffffffu, pt, o);
        sp += __shfl_down_sync(0xffffffffu, sp, o);
        st += __shfl_down_sync(0xffffffffu, st, o);
    }
    __shared__ float sh[5][2];
    if ((threadIdx.x & 31) == 0) {
        int w = threadIdx.x >> 5;
        sh[0][w] = it; sh[1][w] = s; sh[2][w] = pt; sh[3][w] = sp; sh[4][w] = st;
    }
    __syncthreads();
    if (threadIdx.x == 0) {
        float IT = sh[0][0] + sh[0][1];
        float S  = sh[1][0] + sh[1][1];
        float I  = sh[2][0] + sh[2][1];
        float Sp = sh[3][0] + sh[3][1];
        float St = sh[4][0] + sh[4][1];
        float dice   = 1.0f - (2.0f * I + 1e-6f) / (Sp + St + 1e-6f);
        float cldice = 1.0f - 2.0f * IT / S;
        out[0] = 0.8f * dice + 0.2f * cldice;
    }
}

// ---------------------------------------------------------------------------
extern "C" void kernel_launch(void* const* d_in, const int* in_sizes, int n_in,
                              void* d_out, int out_size) {
    const float* pred   = (const float*)d_in[0];
    const float* target = (const float*)d_in[1];
    float* out = (float*)d_out;

    zero_acc<<<1, 448>>>();

    dim3 blk(256);
    dim3 grd(NSTRIP, NZ, NRG);  // 5 x 128 x 2 = 1280 blocks

    skel2<<<grd, blk>>>(0, pred, target);   // iters 1-2: inputs -> A
    skel2<<<grd, blk>>>(1, pred, target);   // iters 3-4: A -> B
    skel2<<<grd, blk>>>(2, pred, target);   // iters 5-6: B -> A
    skel2<<<grd, blk>>>(1, pred, target);   // iters 7-8: A -> B
    skel2_last<<<grd, blk>>>(pred, target); // iters 9-10 + reductions (reads B)

    finalize_kernel<<<1, 64>>>(out);
}